// round 1
// baseline (speedup 1.0000x reference)
#include <cuda_runtime.h>
#include <math.h>

#define B_   4
#define L_   512
#define DM   384
#define NL   4
#define DI   768
#define NS   16
#define DTR  24
#define DC   4
#define VOCAB 1544
#define FEAT 1536
#define M_TOK (B_*L_)   // 2048 tokens

// ---------------- scratch (no allocations allowed) ----------------
__device__ float g_x[M_TOK*DM];
__device__ float g_h[M_TOK*DM];
__device__ float g_xz[M_TOK*2*DI];
__device__ float g_u[M_TOK*DI];
__device__ float g_xdbl[M_TOK*(DTR+2*NS)];   // 56 cols
__device__ float g_delta[M_TOK*DI];
__device__ float g_y[M_TOK*DI];

__device__ __forceinline__ float sigmoidf_(float x){ return 1.f/(1.f+__expf(-x)); }

// ---------------- generic tiled SGEMM: C = A @ W^T (+bias)(+softplus)(+res) --
// A: [M,K] row-major with row stride lda; W: [N,K] row-major; C: [M,N].
template<int BM,int BN,int BK,int TM,int TN,bool HAS_BIAS,bool SOFTPLUS,bool HAS_RES>
__global__ __launch_bounds__(256) void gemm_k(
    const float* __restrict__ A, int lda,
    const float* __restrict__ W,
    const float* __restrict__ bias,
    const float* __restrict__ Res,
    float* __restrict__ C,
    int M, int N, int K)
{
    __shared__ float As[BK][BM+4];
    __shared__ float Ws[BK][BN+4];
    const int tid = threadIdx.x;
    const int ntx = BN/TN;
    const int tx = tid % ntx;
    const int ty = tid / ntx;
    const int m0 = blockIdx.y*BM;
    const int n0 = blockIdx.x*BN;

    float acc[TM][TN];
    #pragma unroll
    for(int i=0;i<TM;i++)
        #pragma unroll
        for(int j=0;j<TN;j++) acc[i][j]=0.f;

    for(int k0=0;k0<K;k0+=BK){
        #pragma unroll
        for(int i=tid;i<BM*BK;i+=256){
            int m=i/BK, k=i%BK;
            int gk=k0+k;
            As[k][m] = (gk<K) ? A[(size_t)(m0+m)*lda + gk] : 0.f;
        }
        #pragma unroll
        for(int i=tid;i<BN*BK;i+=256){
            int n=i/BK, k=i%BK;
            int gn=n0+n, gk=k0+k;
            Ws[k][n] = (gn<N && gk<K) ? W[(size_t)gn*K + gk] : 0.f;
        }
        __syncthreads();
        #pragma unroll
        for(int kk=0;kk<BK;kk++){
            float a[TM], b[TN];
            #pragma unroll
            for(int i=0;i<TM;i++) a[i]=As[kk][ty*TM+i];
            #pragma unroll
            for(int j=0;j<TN;j++) b[j]=Ws[kk][tx*TN+j];
            #pragma unroll
            for(int i=0;i<TM;i++)
                #pragma unroll
                for(int j=0;j<TN;j++) acc[i][j]=fmaf(a[i],b[j],acc[i][j]);
        }
        __syncthreads();
    }
    #pragma unroll
    for(int i=0;i<TM;i++){
        int gm=m0+ty*TM+i;   // M is always a multiple of BM here
        #pragma unroll
        for(int j=0;j<TN;j++){
            int gn=n0+tx*TN+j;
            if(gn<N){
                float v=acc[i][j];
                if(HAS_BIAS) v += bias[gn];
                if(SOFTPLUS) v = fmaxf(v,0.f) + log1pf(__expf(-fabsf(v)));
                if(HAS_RES)  v += Res[(size_t)gm*N+gn];
                C[(size_t)gm*N+gn]=v;
            }
        }
    }
}

// ---------------- RMSNorm: one block per token --------------------
__global__ __launch_bounds__(128) void rmsnorm_k(
    const float* __restrict__ x, const float* __restrict__ w, float* __restrict__ o)
{
    const int row=blockIdx.x, tid=threadIdx.x;
    float s=0.f;
    for(int c=tid;c<DM;c+=128){ float v=x[(size_t)row*DM+c]; s+=v*v; }
    #pragma unroll
    for(int off=16;off;off>>=1) s+=__shfl_xor_sync(0xffffffffu,s,off);
    __shared__ float ws[4];
    if((tid&31)==0) ws[tid>>5]=s;
    __syncthreads();
    if(tid<32){
        float t=(tid<4)?ws[tid]:0.f;
        t+=__shfl_xor_sync(0xffffffffu,t,1);
        t+=__shfl_xor_sync(0xffffffffu,t,2);
        if(tid==0) ws[0]=t;
    }
    __syncthreads();
    const float rms=rsqrtf(ws[0]/(float)DM + 1e-5f);
    for(int c=tid;c<DM;c+=128) o[(size_t)row*DM+c]=x[(size_t)row*DM+c]*rms*w[c];
}

// ---------------- depthwise causal conv(4) + SiLU -----------------
// xz: [M_TOK, 2*DI], uses first DI cols; u: [M_TOK, DI]
__global__ __launch_bounds__(256) void conv_silu_k(
    const float* __restrict__ xz, const float* __restrict__ cw,
    const float* __restrict__ cb, float* __restrict__ u)
{
    int idx=blockIdx.x*256+threadIdx.x;
    if(idx>=M_TOK*DI) return;
    int d=idx%DI, m=idx/DI, l=m%L_;
    float acc=cb[d];
    #pragma unroll
    for(int j=0;j<DC;j++){
        int ls=l-(DC-1)+j;
        if(ls>=0) acc=fmaf(xz[(size_t)(m-(DC-1)+j)*(2*DI)+d], cw[d*DC+j], acc);
    }
    u[idx]=acc*sigmoidf_(acc);
}

// ---------------- selective scan (+ u*D + SiLU gate fused) --------
// grid: (DI/32, B_), 128 threads. 4 threads per channel, 4 states each.
__global__ __launch_bounds__(128) void scan_k(
    const float* __restrict__ delta, const float* __restrict__ u,
    const float* __restrict__ xdbl,  const float* __restrict__ xz,
    const float* __restrict__ Alog,  const float* __restrict__ Dv,
    float* __restrict__ y)
{
    constexpr int CL=64, CPB=32;
    __shared__ float sB[CL][NS], sC[CL][NS];
    __shared__ float sd[CL][CPB], su[CL][CPB], sr[CL][CPB];

    const int b=blockIdx.y, ch0=blockIdx.x*CPB;
    const int tid=threadIdx.x, chl=tid>>2, sub=tid&3, ch=ch0+chl;

    float a[4];
    #pragma unroll
    for(int j=0;j<4;j++) a[j]=-__expf(Alog[ch*NS + sub*4 + j]);
    const float Dd=Dv[ch];
    float h[4]={0.f,0.f,0.f,0.f};
    const int base=b*L_;

    for(int l0=0;l0<L_;l0+=CL){
        for(int i=tid;i<CL*32;i+=128){
            int s=i>>5, c=i&31;
            float v=xdbl[(size_t)(base+l0+s)*(DTR+2*NS) + DTR + c];
            if(c<NS) sB[s][c]=v; else sC[s][c-NS]=v;
        }
        for(int i=tid;i<CL*CPB;i+=128){
            int s=i/CPB, c=i%CPB;
            size_t row=(size_t)(base+l0+s);
            sd[s][c]=delta[row*DI+ch0+c];
            su[s][c]=u[row*DI+ch0+c];
            sr[s][c]=xz[row*(2*DI)+DI+ch0+c];
        }
        __syncthreads();
        #pragma unroll 4
        for(int s=0;s<CL;s++){
            float dt=sd[s][chl], ut=su[s][chl];
            float du=dt*ut;
            float acc=0.f;
            #pragma unroll
            for(int j=0;j<4;j++){
                float dA=__expf(dt*a[j]);
                h[j]=fmaf(dA,h[j], du*sB[s][sub*4+j]);
                acc=fmaf(h[j], sC[s][sub*4+j], acc);
            }
            acc+=__shfl_xor_sync(0xffffffffu,acc,1);
            acc+=__shfl_xor_sync(0xffffffffu,acc,2);
            if(sub==0){
                float r=sr[s][chl];
                y[(size_t)(base+l0+s)*DI+ch]=(acc+ut*Dd)*(r*sigmoidf_(r));
            }
        }
        __syncthreads();
    }
}

// ---------------- host launcher -----------------------------------
extern "C" void kernel_launch(void* const* d_in, const int* in_sizes, int n_in,
                              void* d_out, int out_size)
{
    const float* input_ids = (const float*)d_in[0];
    const float* fc_W      = (const float*)d_in[1];
    const float* fc_b      = (const float*)d_in[2];
    const float* in_proj_W = (const float*)d_in[3];
    const float* conv_W    = (const float*)d_in[4];
    const float* conv_b    = (const float*)d_in[5];
    const float* x_proj_W  = (const float*)d_in[6];
    const float* dt_proj_W = (const float*)d_in[7];
    const float* dt_proj_b = (const float*)d_in[8];
    const float* A_log     = (const float*)d_in[9];
    const float* Dv        = (const float*)d_in[10];
    const float* out_proj_W= (const float*)d_in[11];
    const float* norm_W    = (const float*)d_in[12];
    const float* normf_W   = (const float*)d_in[13];
    const float* head_W    = (const float*)d_in[14];
    float* out = (float*)d_out;

    float *x,*h,*xz,*u,*xdbl,*delta,*y;
    cudaGetSymbolAddress((void**)&x,     g_x);
    cudaGetSymbolAddress((void**)&h,     g_h);
    cudaGetSymbolAddress((void**)&xz,    g_xz);
    cudaGetSymbolAddress((void**)&u,     g_u);
    cudaGetSymbolAddress((void**)&xdbl,  g_xdbl);
    cudaGetSymbolAddress((void**)&delta, g_delta);
    cudaGetSymbolAddress((void**)&y,     g_y);

    // fc: x = input_ids @ fc_W^T + fc_b    (2048 x 1544 -> 2048 x 384)
    gemm_k<128,64,16,8,4,true,false,false>
        <<<dim3(DM/64, M_TOK/128),256>>>(input_ids, VOCAB, fc_W, fc_b, nullptr, x,
                                         M_TOK, DM, VOCAB);

    for(int i=0;i<NL;i++){
        // h = rmsnorm(x) * norm_W[i]
        rmsnorm_k<<<M_TOK,128>>>(x, norm_W+(size_t)i*DM, h);
        // xz = h @ in_proj_W[i]^T          (2048 x 384 -> 2048 x 1536)
        gemm_k<128,64,16,8,4,false,false,false>
            <<<dim3(2*DI/64, M_TOK/128),256>>>(h, DM, in_proj_W+(size_t)i*2*DI*DM,
                                               nullptr, nullptr, xz, M_TOK, 2*DI, DM);
        // u = silu(depthwise_causal_conv(xz[:, :DI]) + conv_b)
        conv_silu_k<<<(M_TOK*DI+255)/256,256>>>(xz, conv_W+(size_t)i*DI*DC,
                                                conv_b+(size_t)i*DI, u);
        // x_dbl = u @ x_proj_W[i]^T        (2048 x 768 -> 2048 x 56)
        gemm_k<32,64,16,2,4,false,false,false>
            <<<dim3(1, M_TOK/32),256>>>(u, DI, x_proj_W+(size_t)i*(DTR+2*NS)*DI,
                                        nullptr, nullptr, xdbl, M_TOK, DTR+2*NS, DI);
        // delta = softplus(x_dbl[:, :24] @ dt_proj_W[i]^T + dt_proj_b[i])
        gemm_k<128,64,16,8,4,true,true,false>
            <<<dim3(DI/64, M_TOK/128),256>>>(xdbl, DTR+2*NS, dt_proj_W+(size_t)i*DI*DTR,
                                             dt_proj_b+(size_t)i*DI, nullptr, delta,
                                             M_TOK, DI, DTR);
        // y = selective_scan(...) fused with +u*D and *silu(res)
        scan_k<<<dim3(DI/32, B_),128>>>(delta, u, xdbl, xz,
                                        A_log+(size_t)i*DI*NS, Dv+(size_t)i*DI, y);
        // x = y @ out_proj_W[i]^T + x      (2048 x 768 -> 2048 x 384, residual)
        gemm_k<128,64,16,8,4,false,false,true>
            <<<dim3(DM/64, M_TOK/128),256>>>(y, DI, out_proj_W+(size_t)i*DM*DI,
                                             nullptr, x, x, M_TOK, DM, DI);
    }

    // final norm + head
    rmsnorm_k<<<M_TOK,128>>>(x, normf_W, h);
    gemm_k<128,64,16,8,4,false,false,false>
        <<<dim3(FEAT/64, M_TOK/128),256>>>(h, DM, head_W, nullptr, nullptr, out,
                                           M_TOK, FEAT, DM);
}

// round 4
// speedup vs baseline: 2.2439x; 2.2439x over previous
#include <cuda_runtime.h>
#include <cuda_fp16.h>
#include <math.h>
#include <stdint.h>

#define B_   4
#define L_   512
#define DM   384
#define NL   4
#define DI   768
#define NS   16
#define DTR  24
#define DC   4
#define VOCAB 1544
#define FEAT 1536
#define M_TOK (B_*L_)   // 2048 tokens

// ---------------- scratch (no allocations allowed) ----------------
__device__ float g_x[M_TOK*DM];
__device__ float g_h[M_TOK*DM];
__device__ float g_xz[M_TOK*2*DI];
__device__ float g_u[M_TOK*DI];
__device__ float g_xdbl[M_TOK*(DTR+2*NS)];   // 56 cols
__device__ float g_delta[M_TOK*DI];
__device__ float g_y[M_TOK*DI];

__device__ __forceinline__ float sigmoidf_(float x){ return 1.f/(1.f+__expf(-x)); }

__device__ __forceinline__ uint32_t smem_u32(const void* p){
    uint32_t a;
    asm("{ .reg .u64 t; cvta.to.shared.u64 t, %1; cvt.u32.u64 %0, t; }" : "=r"(a) : "l"(p));
    return a;
}
__device__ __forceinline__ void ldsm_x4(uint32_t&r0,uint32_t&r1,uint32_t&r2,uint32_t&r3,uint32_t a){
    asm volatile("ldmatrix.sync.aligned.m8n8.x4.shared.b16 {%0,%1,%2,%3},[%4];"
        : "=r"(r0),"=r"(r1),"=r"(r2),"=r"(r3) : "r"(a));
}
__device__ __forceinline__ void mma16816(float&c0,float&c1,float&c2,float&c3,
    uint32_t a0,uint32_t a1,uint32_t a2,uint32_t a3,uint32_t b0,uint32_t b1){
    asm volatile("mma.sync.aligned.m16n8k16.row.col.f32.f16.f16.f32 "
        "{%0,%1,%2,%3},{%4,%5,%6,%7},{%8,%9},{%0,%1,%2,%3};"
        : "+f"(c0),"+f"(c1),"+f"(c2),"+f"(c3)
        : "r"(a0),"r"(a1),"r"(a2),"r"(a3),"r"(b0),"r"(b1));
}

// ============ HMMA f16 GEMM: C[M,Nout] = A[M,K] @ W[Wn,K]^T (+epilogue) ======
// BM=128, BN=64, BK=64. 256 threads = 8 warps (4 in m, 2 in n), warp tile 32x32.
template<bool HAS_BIAS,bool SOFTPLUS,bool HAS_RES>
__global__ void __launch_bounds__(256) hgemm_k(
    const float* __restrict__ A, int lda, int Kvalid, int nChunks,
    const float* __restrict__ W, int Wn,
    const float* __restrict__ bias, const float* __restrict__ Res,
    float* __restrict__ C, int Nout)
{
    constexpr int PAD = 72;                 // halves per row (64 + 8) => 144B stride
    __shared__ __half sA[128*PAD];
    __shared__ __half sB[64*PAD];

    const int tid = threadIdx.x;
    const int w   = tid>>5, l = tid&31;
    const int wm  = w>>1,  wn = w&1;        // warp grid 4x2
    const int m0  = blockIdx.y*128, n0 = blockIdx.x*64;

    const uint32_t sAb = smem_u32(sA), sBb = smem_u32(sB);

    float acc[2][4][4];
    #pragma unroll
    for(int i=0;i<2;i++)
        #pragma unroll
        for(int j=0;j<4;j++)
            #pragma unroll
            for(int q=0;q<4;q++) acc[i][j][q]=0.f;

    float4 ra[8], rb[4];

    auto loadA=[&](int c){
        const int k0=c*64;
        #pragma unroll
        for(int j=0;j<8;j++){
            int idx=tid+256*j, row=idx>>4, c4=idx&15, gk=k0+c4*4;
            ra[j] = (gk<Kvalid) ? *(const float4*)(A+(size_t)(m0+row)*lda+gk)
                                : make_float4(0.f,0.f,0.f,0.f);
        }
    };
    auto loadB=[&](int c){
        const int k0=c*64;
        #pragma unroll
        for(int j=0;j<4;j++){
            int idx=tid+256*j, row=idx>>4, c4=idx&15, gk=k0+c4*4, gn=n0+row;
            rb[j] = (gn<Wn && gk<Kvalid) ? *(const float4*)(W+(size_t)gn*Kvalid+gk)
                                         : make_float4(0.f,0.f,0.f,0.f);
        }
    };
    auto storeA=[&](){
        #pragma unroll
        for(int j=0;j<8;j++){
            int idx=tid+256*j, row=idx>>4, c4=idx&15;
            __half2 h0=__floats2half2_rn(ra[j].x,ra[j].y);
            __half2 h1=__floats2half2_rn(ra[j].z,ra[j].w);
            uint2 v; v.x=*(uint32_t*)&h0; v.y=*(uint32_t*)&h1;
            *(uint2*)(sA+row*PAD+c4*4)=v;
        }
    };
    auto storeB=[&](){
        #pragma unroll
        for(int j=0;j<4;j++){
            int idx=tid+256*j, row=idx>>4, c4=idx&15;
            __half2 h0=__floats2half2_rn(rb[j].x,rb[j].y);
            __half2 h1=__floats2half2_rn(rb[j].z,rb[j].w);
            uint2 v; v.x=*(uint32_t*)&h0; v.y=*(uint32_t*)&h1;
            *(uint2*)(sB+row*PAD+c4*4)=v;
        }
    };

    loadA(0); loadB(0);
    for(int c=0;c<nChunks;c++){
        storeA(); storeB();
        __syncthreads();
        if(c+1<nChunks){ loadA(c+1); loadB(c+1); }
        #pragma unroll
        for(int ks=0;ks<4;ks++){
            // A fragments: 2 m-tiles of 16
            uint32_t af[2][4];
            #pragma unroll
            for(int mi=0;mi<2;mi++){
                int row = wm*32 + mi*16 + (l&15);
                int col = ks*16 + (l>>4)*8;
                ldsm_x4(af[mi][0],af[mi][1],af[mi][2],af[mi][3],
                        sAb + (row*PAD+col)*2);
            }
            // B fragments: W[n][k] row-major IS col-major k x n => non-trans ldmatrix.
            // lanes 0-7: n 0-7 @ k0 | 8-15: n 0-7 @ k0+8 | 16-23: n 8-15 @ k0 | 24-31: n 8-15 @ k0+8
            uint32_t bf[4][2];
            #pragma unroll
            for(int np=0;np<2;np++){
                int row = wn*32 + np*16 + ((l>>4)<<3) + (l&7);
                int col = ks*16 + (((l>>3)&1)<<3);
                uint32_t r0,r1,r2,r3;
                ldsm_x4(r0,r1,r2,r3, sBb + (row*PAD+col)*2);
                bf[np*2][0]=r0; bf[np*2][1]=r1; bf[np*2+1][0]=r2; bf[np*2+1][1]=r3;
            }
            #pragma unroll
            for(int mi=0;mi<2;mi++)
                #pragma unroll
                for(int ni=0;ni<4;ni++)
                    mma16816(acc[mi][ni][0],acc[mi][ni][1],acc[mi][ni][2],acc[mi][ni][3],
                             af[mi][0],af[mi][1],af[mi][2],af[mi][3],
                             bf[ni][0],bf[ni][1]);
        }
        __syncthreads();
    }

    // epilogue: c0/c1 at (row, col), c2/c3 at (row+8, col)
    const int grp=l>>2, tig=l&3;
    #pragma unroll
    for(int mi=0;mi<2;mi++){
        int gm0 = m0 + wm*32 + mi*16 + grp;
        #pragma unroll
        for(int ni=0;ni<4;ni++){
            int gn = n0 + wn*32 + ni*8 + tig*2;
            #pragma unroll
            for(int half=0; half<2; half++){
                int gm = gm0 + half*8;
                float v0=acc[mi][ni][half*2], v1=acc[mi][ni][half*2+1];
                if(gn<Nout){
                    if(HAS_BIAS){ v0+=bias[gn]; v1+=bias[gn+1]; }
                    if(SOFTPLUS){
                        v0 = fmaxf(v0,0.f)+log1pf(__expf(-fabsf(v0)));
                        v1 = fmaxf(v1,0.f)+log1pf(__expf(-fabsf(v1)));
                    }
                    if(HAS_RES){
                        v0 += Res[(size_t)gm*Nout+gn];
                        v1 += Res[(size_t)gm*Nout+gn+1];
                    }
                    C[(size_t)gm*Nout+gn]   = v0;
                    C[(size_t)gm*Nout+gn+1] = v1;
                }
            }
        }
    }
}

// ---------------- RMSNorm: one block per token --------------------
__global__ __launch_bounds__(128) void rmsnorm_k(
    const float* __restrict__ x, const float* __restrict__ w, float* __restrict__ o)
{
    const int row=blockIdx.x, tid=threadIdx.x;
    float s=0.f;
    for(int c=tid;c<DM;c+=128){ float v=x[(size_t)row*DM+c]; s+=v*v; }
    #pragma unroll
    for(int off=16;off;off>>=1) s+=__shfl_xor_sync(0xffffffffu,s,off);
    __shared__ float ws[4];
    if((tid&31)==0) ws[tid>>5]=s;
    __syncthreads();
    if(tid<32){
        float t=(tid<4)?ws[tid]:0.f;
        t+=__shfl_xor_sync(0xffffffffu,t,1);
        t+=__shfl_xor_sync(0xffffffffu,t,2);
        if(tid==0) ws[0]=t;
    }
    __syncthreads();
    const float rms=rsqrtf(ws[0]/(float)DM + 1e-5f);
    for(int c=tid;c<DM;c+=128) o[(size_t)row*DM+c]=x[(size_t)row*DM+c]*rms*w[c];
}

// ---------------- depthwise causal conv(4) + SiLU -----------------
__global__ __launch_bounds__(256) void conv_silu_k(
    const float* __restrict__ xz, const float* __restrict__ cw,
    const float* __restrict__ cb, float* __restrict__ u)
{
    int idx=blockIdx.x*256+threadIdx.x;
    if(idx>=M_TOK*DI) return;
    int d=idx%DI, m=idx/DI, l=m%L_;
    float acc=cb[d];
    #pragma unroll
    for(int j=0;j<DC;j++){
        int ls=l-(DC-1)+j;
        if(ls>=0) acc=fmaf(xz[(size_t)(m-(DC-1)+j)*(2*DI)+d], cw[d*DC+j], acc);
    }
    u[idx]=acc*sigmoidf_(acc);
}

// ---------------- selective scan (+ u*D + SiLU gate fused) --------
__global__ __launch_bounds__(128) void scan_k(
    const float* __restrict__ delta, const float* __restrict__ u,
    const float* __restrict__ xdbl,  const float* __restrict__ xz,
    const float* __restrict__ Alog,  const float* __restrict__ Dv,
    float* __restrict__ y)
{
    constexpr int CL=64, CPB=32;
    __shared__ float sB[CL][NS], sC[CL][NS];
    __shared__ float sd[CL][CPB], su[CL][CPB], sr[CL][CPB];

    const int b=blockIdx.y, ch0=blockIdx.x*CPB;
    const int tid=threadIdx.x, chl=tid>>2, sub=tid&3, ch=ch0+chl;

    float a[4];
    #pragma unroll
    for(int j=0;j<4;j++) a[j]=-__expf(Alog[ch*NS + sub*4 + j]);
    const float Dd=Dv[ch];
    float h[4]={0.f,0.f,0.f,0.f};
    const int base=b*L_;

    for(int l0=0;l0<L_;l0+=CL){
        for(int i=tid;i<CL*32;i+=128){
            int s=i>>5, c=i&31;
            float v=xdbl[(size_t)(base+l0+s)*(DTR+2*NS) + DTR + c];
            if(c<NS) sB[s][c]=v; else sC[s][c-NS]=v;
        }
        for(int i=tid;i<CL*CPB;i+=128){
            int s=i/CPB, c=i%CPB;
            size_t row=(size_t)(base+l0+s);
            sd[s][c]=delta[row*DI+ch0+c];
            su[s][c]=u[row*DI+ch0+c];
            sr[s][c]=xz[row*(2*DI)+DI+ch0+c];
        }
        __syncthreads();
        #pragma unroll 4
        for(int s=0;s<CL;s++){
            float dt=sd[s][chl], ut=su[s][chl];
            float du=dt*ut;
            float acc=0.f;
            #pragma unroll
            for(int j=0;j<4;j++){
                float dA=__expf(dt*a[j]);
                h[j]=fmaf(dA,h[j], du*sB[s][sub*4+j]);
                acc=fmaf(h[j], sC[s][sub*4+j], acc);
            }
            acc+=__shfl_xor_sync(0xffffffffu,acc,1);
            acc+=__shfl_xor_sync(0xffffffffu,acc,2);
            if(sub==0){
                float r=sr[s][chl];
                y[(size_t)(base+l0+s)*DI+ch]=(acc+ut*Dd)*(r*sigmoidf_(r));
            }
        }
        __syncthreads();
    }
}

// ---------------- host launcher -----------------------------------
extern "C" void kernel_launch(void* const* d_in, const int* in_sizes, int n_in,
                              void* d_out, int out_size)
{
    const float* input_ids = (const float*)d_in[0];
    const float* fc_W      = (const float*)d_in[1];
    const float* fc_b      = (const float*)d_in[2];
    const float* in_proj_W = (const float*)d_in[3];
    const float* conv_W    = (const float*)d_in[4];
    const float* conv_b    = (const float*)d_in[5];
    const float* x_proj_W  = (const float*)d_in[6];
    const float* dt_proj_W = (const float*)d_in[7];
    const float* dt_proj_b = (const float*)d_in[8];
    const float* A_log     = (const float*)d_in[9];
    const float* Dv        = (const float*)d_in[10];
    const float* out_proj_W= (const float*)d_in[11];
    const float* norm_W    = (const float*)d_in[12];
    const float* normf_W   = (const float*)d_in[13];
    const float* head_W    = (const float*)d_in[14];
    float* out = (float*)d_out;

    float *x,*h,*xz,*u,*xdbl,*delta,*y;
    cudaGetSymbolAddress((void**)&x,     g_x);
    cudaGetSymbolAddress((void**)&h,     g_h);
    cudaGetSymbolAddress((void**)&xz,    g_xz);
    cudaGetSymbolAddress((void**)&u,     g_u);
    cudaGetSymbolAddress((void**)&xdbl,  g_xdbl);
    cudaGetSymbolAddress((void**)&delta, g_delta);
    cudaGetSymbolAddress((void**)&y,     g_y);

    // fc: x = input_ids @ fc_W^T + fc_b   (2048x1544 -> 2048x384)
    hgemm_k<true,false,false><<<dim3(6,16),256>>>(
        input_ids, VOCAB, VOCAB, 25, fc_W, DM, fc_b, nullptr, x, DM);

    for(int i=0;i<NL;i++){
        rmsnorm_k<<<M_TOK,128>>>(x, norm_W+(size_t)i*DM, h);
        // xz = h @ in_proj_W^T  (2048x384 -> 2048x1536)
        hgemm_k<false,false,false><<<dim3(24,16),256>>>(
            h, DM, DM, 6, in_proj_W+(size_t)i*2*DI*DM, 2*DI, nullptr, nullptr, xz, 2*DI);
        conv_silu_k<<<(M_TOK*DI+255)/256,256>>>(xz, conv_W+(size_t)i*DI*DC,
                                                conv_b+(size_t)i*DI, u);
        // x_dbl = u @ x_proj_W^T  (2048x768 -> 2048x56)
        hgemm_k<false,false,false><<<dim3(1,16),256>>>(
            u, DI, DI, 12, x_proj_W+(size_t)i*(DTR+2*NS)*DI, DTR+2*NS, nullptr, nullptr,
            xdbl, DTR+2*NS);
        // delta = softplus(x_dbl[:, :24] @ dt_proj_W^T + b)
        hgemm_k<true,true,false><<<dim3(12,16),256>>>(
            xdbl, DTR+2*NS, DTR, 1, dt_proj_W+(size_t)i*DI*DTR, DI,
            dt_proj_b+(size_t)i*DI, nullptr, delta, DI);
        scan_k<<<dim3(DI/32, B_),128>>>(delta, u, xdbl, xz,
                                        A_log+(size_t)i*DI*NS, Dv+(size_t)i*DI, y);
        // x = y @ out_proj_W^T + x  (2048x768 -> 2048x384, residual)
        hgemm_k<false,false,true><<<dim3(6,16),256>>>(
            y, DI, DI, 12, out_proj_W+(size_t)i*DM*DI, DM, nullptr, x, x, DM);
    }

    rmsnorm_k<<<M_TOK,128>>>(x, normf_W, h);
    // out = h @ head_W^T  (2048x384 -> 2048x1536)
    hgemm_k<false,false,false><<<dim3(24,16),256>>>(
        h, DM, DM, 6, head_W, FEAT, nullptr, nullptr, out, FEAT);
}

// round 5
// speedup vs baseline: 2.4536x; 1.0935x over previous
#include <cuda_runtime.h>
#include <cuda_fp16.h>
#include <math.h>
#include <stdint.h>

#define B_   4
#define L_   512
#define DM   384
#define NL   4
#define DI   768
#define NS   16
#define DTR  24
#define DC   4
#define VOCAB 1544
#define FEAT 1536
#define M_TOK (B_*L_)   // 2048 tokens
#define VPAD 1600       // VOCAB padded to 64-multiple

// ---------------- scratch (no allocations allowed) ----------------
__device__ float g_x[M_TOK*DM];
__device__ float g_xz[M_TOK*2*DI];
__device__ float g_u[M_TOK*DI];
__device__ float g_xdbl[M_TOK*(DTR+2*NS)];   // 56 cols (f32, for scan)
__device__ float g_delta[M_TOK*DI];

__device__ __half g_ids16[M_TOK*VPAD];       // padded input_ids
__device__ __half g_fcW16[DM*VPAD];
__device__ __half g_inW16[NL*2*DI*DM];
__device__ __half g_xW16[NL*64*DI];          // N padded 56->64
__device__ __half g_dtW16[NL*DI*64];         // K padded 24->64
__device__ __half g_outW16[NL*DM*DI];
__device__ __half g_headW16[FEAT*DM];
__device__ __half g_h16[M_TOK*DM];
__device__ __half g_u16[M_TOK*DI];
__device__ __half g_y16[M_TOK*DI];
__device__ __half g_xdbl16[M_TOK*64];        // padded 56->64 (zeros in pad)

__device__ __forceinline__ float sigmoidf_(float x){ return 1.f/(1.f+__expf(-x)); }

__device__ __forceinline__ uint32_t smem_u32(const void* p){
    uint32_t a;
    asm("{ .reg .u64 t; cvta.to.shared.u64 t, %1; cvt.u32.u64 %0, t; }" : "=r"(a) : "l"(p));
    return a;
}
__device__ __forceinline__ void cp16(uint32_t s, const void* g){
    asm volatile("cp.async.cg.shared.global [%0],[%1],16;"::"r"(s),"l"(g));
}
__device__ __forceinline__ void cp_commit(){ asm volatile("cp.async.commit_group;"); }
template<int N> __device__ __forceinline__ void cp_wait(){
    asm volatile("cp.async.wait_group %0;"::"n"(N));
}
__device__ __forceinline__ void ldsm_x4(uint32_t&r0,uint32_t&r1,uint32_t&r2,uint32_t&r3,uint32_t a){
    asm volatile("ldmatrix.sync.aligned.m8n8.x4.shared.b16 {%0,%1,%2,%3},[%4];"
        : "=r"(r0),"=r"(r1),"=r"(r2),"=r"(r3) : "r"(a));
}
__device__ __forceinline__ void mma16816(float&c0,float&c1,float&c2,float&c3,
    uint32_t a0,uint32_t a1,uint32_t a2,uint32_t a3,uint32_t b0,uint32_t b1){
    asm volatile("mma.sync.aligned.m16n8k16.row.col.f32.f16.f16.f32 "
        "{%0,%1,%2,%3},{%4,%5,%6,%7},{%8,%9},{%0,%1,%2,%3};"
        : "+f"(c0),"+f"(c1),"+f"(c2),"+f"(c3)
        : "r"(a0),"r"(a1),"r"(a2),"r"(a3),"r"(b0),"r"(b1));
}
// swizzled smem byte offset: row (0..BM-1), c16 = 16B column (0..7)
__device__ __forceinline__ uint32_t swz(int row, int c16){
    return (uint32_t)(row*128 + (((c16)^(row&7))<<4));
}

// ============ HMMA f16 GEMM v2: C[M,Nout] = A[M,K] @ W[N,K]^T ================
// MW in {2,4}: BM = MW*32; BN=64; BK=64. 256 thr = 8 warps: MW m-warps x (8/MW) n-warps.
// A,W are f16; lda/ldw are padded K (multiple of 8); no bounds checks in loaders.
template<int MW,bool HAS_BIAS,bool SOFTPLUS,bool HAS_RES,bool WF16>
__global__ void __launch_bounds__(256) hgemm2(
    const __half* __restrict__ A, int lda, int nChunks,
    const __half* __restrict__ W, int ldw,
    const float* __restrict__ bias, const float* __restrict__ Res,
    float* __restrict__ C, int Nout, __half* __restrict__ C16, int ld16)
{
    constexpr int BM = MW*32;
    constexpr int NI = MW;                  // n-tiles (of 8) per warp
    constexpr int NWN = 8/MW;               // warps in n
    constexpr int A_STG = BM*64;            // halves per stage
    constexpr int B_STG = 64*64;

    __shared__ __half sA[2*A_STG];
    __shared__ __half sB[2*B_STG];

    const int tid = threadIdx.x;
    const int w   = tid>>5, l = tid&31;
    const int wm  = w / NWN, wn = w % NWN;
    const int m0  = blockIdx.y*BM, n0 = blockIdx.x*64;

    const uint32_t sAb = smem_u32(sA), sBb = smem_u32(sB);
    const __half* Abase = A + (size_t)m0*lda;
    const __half* Wbase = W + (size_t)n0*ldw;

    float acc[2][NI][4];
    #pragma unroll
    for(int i=0;i<2;i++)
        #pragma unroll
        for(int j=0;j<NI;j++)
            #pragma unroll
            for(int q=0;q<4;q++) acc[i][j][q]=0.f;

    auto issue=[&](int c){
        const int st=c&1, k0=c*64;
        const uint32_t sa = sAb + st*A_STG*2;
        const uint32_t sbp = sBb + st*B_STG*2;
        #pragma unroll
        for(int j=0;j<MW;j++){
            int g=tid+256*j, row=g>>3, c16=g&7;
            cp16(sa + swz(row,c16), Abase + (size_t)row*lda + k0 + c16*8);
        }
        #pragma unroll
        for(int j=0;j<2;j++){
            int g=tid+256*j, row=g>>3, c16=g&7;
            cp16(sbp + swz(row,c16), Wbase + (size_t)row*ldw + k0 + c16*8);
        }
        cp_commit();
    };

    issue(0);
    for(int c=0;c<nChunks;c++){
        if(c+1<nChunks){ issue(c+1); cp_wait<1>(); }
        else           { cp_wait<0>(); }
        __syncthreads();
        const int st=c&1;
        const uint32_t aB = sAb + st*A_STG*2;
        const uint32_t bB = sBb + st*B_STG*2;
        #pragma unroll
        for(int ks=0;ks<4;ks++){
            uint32_t af[2][4];
            #pragma unroll
            for(int mi=0;mi<2;mi++){
                int row = wm*32 + mi*16 + (l&15);
                int c16 = ks*2 + (l>>4);
                ldsm_x4(af[mi][0],af[mi][1],af[mi][2],af[mi][3], aB + swz(row,c16));
            }
            uint32_t bf[NI][2];
            #pragma unroll
            for(int np=0;np<NI/2;np++){
                int row = wn*(8*MW) + np*16 + ((l>>4)<<3) + (l&7);
                int c16 = ks*2 + ((l>>3)&1);
                uint32_t r0,r1,r2,r3;
                ldsm_x4(r0,r1,r2,r3, bB + swz(row,c16));
                bf[np*2][0]=r0; bf[np*2][1]=r1; bf[np*2+1][0]=r2; bf[np*2+1][1]=r3;
            }
            #pragma unroll
            for(int mi=0;mi<2;mi++)
                #pragma unroll
                for(int ni=0;ni<NI;ni++)
                    mma16816(acc[mi][ni][0],acc[mi][ni][1],acc[mi][ni][2],acc[mi][ni][3],
                             af[mi][0],af[mi][1],af[mi][2],af[mi][3],
                             bf[ni][0],bf[ni][1]);
        }
        __syncthreads();
    }

    const int grp=l>>2, tig=l&3;
    #pragma unroll
    for(int mi=0;mi<2;mi++){
        int gm0 = m0 + wm*32 + mi*16 + grp;
        #pragma unroll
        for(int ni=0;ni<NI;ni++){
            int gn = n0 + wn*(8*MW) + ni*8 + tig*2;
            #pragma unroll
            for(int half=0; half<2; half++){
                int gm = gm0 + half*8;
                float v0=acc[mi][ni][half*2], v1=acc[mi][ni][half*2+1];
                if(gn<Nout){
                    if(HAS_BIAS){ v0+=bias[gn]; v1+=bias[gn+1]; }
                    if(SOFTPLUS){
                        v0 = fmaxf(v0,0.f)+log1pf(__expf(-fabsf(v0)));
                        v1 = fmaxf(v1,0.f)+log1pf(__expf(-fabsf(v1)));
                    }
                    if(HAS_RES){
                        v0 += Res[(size_t)gm*Nout+gn];
                        v1 += Res[(size_t)gm*Nout+gn+1];
                    }
                    C[(size_t)gm*Nout+gn]   = v0;
                    C[(size_t)gm*Nout+gn+1] = v1;
                }
                if(WF16){
                    if(gn<ld16){
                        __half2 hv = __floats2half2_rn(gn<Nout?v0:0.f, gn+1<Nout?v1:0.f);
                        *(__half2*)(C16 + (size_t)gm*ld16 + gn) = hv;
                    }
                }
            }
        }
    }
}

// ---------------- converters (run each replay; ~6us total) --------
__global__ __launch_bounds__(256) void cvt_pad_k(
    const float* __restrict__ src, __half* __restrict__ dst, int rows, int sc, int dc)
{
    int i=blockIdx.x*256+threadIdx.x;
    if(i>=rows*dc) return;
    int r=i/dc, c=i%dc;
    dst[i]=__float2half(c<sc ? src[(size_t)r*sc+c] : 0.f);
}
__global__ __launch_bounds__(256) void cvt_plain_k(
    const float* __restrict__ src, __half* __restrict__ dst, int n)
{
    int i=blockIdx.x*256+threadIdx.x;
    if(i<n) dst[i]=__float2half(src[i]);
}
__global__ __launch_bounds__(256) void cvt_padrow_k(
    const float* __restrict__ src, __half* __restrict__ dst, int Lc, int dr, int sr, int cols)
{
    int i=blockIdx.x*256+threadIdx.x;
    if(i>=Lc*dr*cols) return;
    int c=i%cols, r=(i/cols)%dr, lay=i/(cols*dr);
    dst[i]=__float2half(r<sr ? src[((size_t)lay*sr+r)*cols+c] : 0.f);
}

// ---------------- RMSNorm -> f16 ----------------------------------
__global__ __launch_bounds__(128) void rmsnorm_k(
    const float* __restrict__ x, const float* __restrict__ w, __half* __restrict__ o)
{
    const int row=blockIdx.x, tid=threadIdx.x;
    float s=0.f;
    for(int c=tid;c<DM;c+=128){ float v=x[(size_t)row*DM+c]; s+=v*v; }
    #pragma unroll
    for(int off=16;off;off>>=1) s+=__shfl_xor_sync(0xffffffffu,s,off);
    __shared__ float ws[4];
    if((tid&31)==0) ws[tid>>5]=s;
    __syncthreads();
    if(tid<32){
        float t=(tid<4)?ws[tid]:0.f;
        t+=__shfl_xor_sync(0xffffffffu,t,1);
        t+=__shfl_xor_sync(0xffffffffu,t,2);
        if(tid==0) ws[0]=t;
    }
    __syncthreads();
    const float rms=rsqrtf(ws[0]/(float)DM + 1e-5f);
    for(int c=tid;c<DM;c+=128)
        o[(size_t)row*DM+c]=__float2half(x[(size_t)row*DM+c]*rms*w[c]);
}

// ---------------- depthwise causal conv(4) + SiLU -> f32 + f16 ----
__global__ __launch_bounds__(256) void conv_silu_k(
    const float* __restrict__ xz, const float* __restrict__ cw,
    const float* __restrict__ cb, float* __restrict__ u, __half* __restrict__ u16)
{
    int idx=blockIdx.x*256+threadIdx.x;
    if(idx>=M_TOK*DI) return;
    int d=idx%DI, m=idx/DI, l=m%L_;
    float acc=cb[d];
    #pragma unroll
    for(int j=0;j<DC;j++){
        int ls=l-(DC-1)+j;
        if(ls>=0) acc=fmaf(xz[(size_t)(m-(DC-1)+j)*(2*DI)+d], cw[d*DC+j], acc);
    }
    float v=acc*sigmoidf_(acc);
    u[idx]=v;
    u16[idx]=__float2half(v);
}

// ---------------- selective scan -> f16 y -------------------------
__global__ __launch_bounds__(128) void scan_k(
    const float* __restrict__ delta, const float* __restrict__ u,
    const float* __restrict__ xdbl,  const float* __restrict__ xz,
    const float* __restrict__ Alog,  const float* __restrict__ Dv,
    __half* __restrict__ y)
{
    constexpr int CL=64, CPB=32;
    __shared__ float sB[CL][NS], sC[CL][NS];
    __shared__ float sd[CL][CPB], su[CL][CPB], sr[CL][CPB];

    const int b=blockIdx.y, ch0=blockIdx.x*CPB;
    const int tid=threadIdx.x, chl=tid>>2, sub=tid&3, ch=ch0+chl;

    float a[4];
    #pragma unroll
    for(int j=0;j<4;j++) a[j]=-__expf(Alog[ch*NS + sub*4 + j]);
    const float Dd=Dv[ch];
    float h[4]={0.f,0.f,0.f,0.f};
    const int base=b*L_;

    for(int l0=0;l0<L_;l0+=CL){
        for(int i=tid;i<CL*32;i+=128){
            int s=i>>5, c=i&31;
            float v=xdbl[(size_t)(base+l0+s)*(DTR+2*NS) + DTR + c];
            if(c<NS) sB[s][c]=v; else sC[s][c-NS]=v;
        }
        for(int i=tid;i<CL*CPB;i+=128){
            int s=i/CPB, c=i%CPB;
            size_t row=(size_t)(base+l0+s);
            sd[s][c]=delta[row*DI+ch0+c];
            su[s][c]=u[row*DI+ch0+c];
            sr[s][c]=xz[row*(2*DI)+DI+ch0+c];
        }
        __syncthreads();
        #pragma unroll 4
        for(int s=0;s<CL;s++){
            float dt=sd[s][chl], ut=su[s][chl];
            float du=dt*ut;
            float acc=0.f;
            #pragma unroll
            for(int j=0;j<4;j++){
                float dA=__expf(dt*a[j]);
                h[j]=fmaf(dA,h[j], du*sB[s][sub*4+j]);
                acc=fmaf(h[j], sC[s][sub*4+j], acc);
            }
            acc+=__shfl_xor_sync(0xffffffffu,acc,1);
            acc+=__shfl_xor_sync(0xffffffffu,acc,2);
            if(sub==0){
                float r=sr[s][chl];
                y[(size_t)(base+l0+s)*DI+ch]=__float2half((acc+ut*Dd)*(r*sigmoidf_(r)));
            }
        }
        __syncthreads();
    }
}

// ---------------- host launcher -----------------------------------
extern "C" void kernel_launch(void* const* d_in, const int* in_sizes, int n_in,
                              void* d_out, int out_size)
{
    const float* input_ids = (const float*)d_in[0];
    const float* fc_W      = (const float*)d_in[1];
    const float* fc_b      = (const float*)d_in[2];
    const float* in_proj_W = (const float*)d_in[3];
    const float* conv_W    = (const float*)d_in[4];
    const float* conv_b    = (const float*)d_in[5];
    const float* x_proj_W  = (const float*)d_in[6];
    const float* dt_proj_W = (const float*)d_in[7];
    const float* dt_proj_b = (const float*)d_in[8];
    const float* A_log     = (const float*)d_in[9];
    const float* Dv        = (const float*)d_in[10];
    const float* out_proj_W= (const float*)d_in[11];
    const float* norm_W    = (const float*)d_in[12];
    const float* normf_W   = (const float*)d_in[13];
    const float* head_W    = (const float*)d_in[14];
    float* out = (float*)d_out;

    float *x,*xz,*u,*xdbl,*delta;
    __half *ids16,*fcW16,*inW16,*xW16,*dtW16,*outW16,*headW16,*h16,*u16,*y16,*xdbl16;
    cudaGetSymbolAddress((void**)&x,      g_x);
    cudaGetSymbolAddress((void**)&xz,     g_xz);
    cudaGetSymbolAddress((void**)&u,      g_u);
    cudaGetSymbolAddress((void**)&xdbl,   g_xdbl);
    cudaGetSymbolAddress((void**)&delta,  g_delta);
    cudaGetSymbolAddress((void**)&ids16,  g_ids16);
    cudaGetSymbolAddress((void**)&fcW16,  g_fcW16);
    cudaGetSymbolAddress((void**)&inW16,  g_inW16);
    cudaGetSymbolAddress((void**)&xW16,   g_xW16);
    cudaGetSymbolAddress((void**)&dtW16,  g_dtW16);
    cudaGetSymbolAddress((void**)&outW16, g_outW16);
    cudaGetSymbolAddress((void**)&headW16,g_headW16);
    cudaGetSymbolAddress((void**)&h16,    g_h16);
    cudaGetSymbolAddress((void**)&u16,    g_u16);
    cudaGetSymbolAddress((void**)&y16,    g_y16);
    cudaGetSymbolAddress((void**)&xdbl16, g_xdbl16);

    auto cdiv=[](int a,int b){ return (a+b-1)/b; };

    // ---- pre-convert weights + ids to f16 (padded) ----
    cvt_pad_k<<<cdiv(M_TOK*VPAD,256),256>>>(input_ids, ids16, M_TOK, VOCAB, VPAD);
    cvt_pad_k<<<cdiv(DM*VPAD,256),256>>>(fc_W, fcW16, DM, VOCAB, VPAD);
    cvt_plain_k<<<cdiv(NL*2*DI*DM,256),256>>>(in_proj_W, inW16, NL*2*DI*DM);
    cvt_padrow_k<<<cdiv(NL*64*DI,256),256>>>(x_proj_W, xW16, NL, 64, DTR+2*NS, DI);
    cvt_pad_k<<<cdiv(NL*DI*64,256),256>>>(dt_proj_W, dtW16, NL*DI, DTR, 64);
    cvt_plain_k<<<cdiv(NL*DM*DI,256),256>>>(out_proj_W, outW16, NL*DM*DI);
    cvt_plain_k<<<cdiv(FEAT*DM,256),256>>>(head_W, headW16, FEAT*DM);

    // fc: x = ids @ fc_W^T + b   (2048x1600(pad) -> 2048x384), MW=2 -> 192 blocks
    hgemm2<2,true,false,false,false><<<dim3(6,32),256>>>(
        ids16, VPAD, 25, fcW16, VPAD, fc_b, nullptr, x, DM, nullptr, 0);

    for(int i=0;i<NL;i++){
        rmsnorm_k<<<M_TOK,128>>>(x, norm_W+(size_t)i*DM, h16);
        // xz = h @ in_proj^T  (K=384, 6 chunks), 384 blocks
        hgemm2<4,false,false,false,false><<<dim3(24,16),256>>>(
            h16, DM, 6, inW16+(size_t)i*2*DI*DM, DM, nullptr, nullptr, xz, 2*DI, nullptr, 0);
        conv_silu_k<<<cdiv(M_TOK*DI,256),256>>>(xz, conv_W+(size_t)i*DI*DC,
                                                conv_b+(size_t)i*DI, u, u16);
        // x_dbl = u @ x_proj^T  (K=768, 12 chunks), MW=2 -> 32 blocks; dual f32+f16 out
        hgemm2<2,false,false,false,true><<<dim3(1,32),256>>>(
            u16, DI, 12, xW16+(size_t)i*64*DI, DI, nullptr, nullptr,
            xdbl, DTR+2*NS, xdbl16, 64);
        // delta = softplus(xdbl16 @ dtW16^T + b)  (K=64 padded, 1 chunk), 192 blocks
        hgemm2<4,true,true,false,false><<<dim3(12,16),256>>>(
            xdbl16, 64, 1, dtW16+(size_t)i*DI*64, 64,
            dt_proj_b+(size_t)i*DI, nullptr, delta, DI, nullptr, 0);
        scan_k<<<dim3(DI/32, B_),128>>>(delta, u, xdbl, xz,
                                        A_log+(size_t)i*DI*NS, Dv+(size_t)i*DI, y16);
        // x = y @ out_proj^T + x  (K=768, 12 chunks), MW=2 -> 192 blocks
        hgemm2<2,false,false,true,false><<<dim3(6,32),256>>>(
            y16, DI, 12, outW16+(size_t)i*DM*DI, DI, nullptr, x, x, DM, nullptr, 0);
    }

    rmsnorm_k<<<M_TOK,128>>>(x, normf_W, h16);
    // out = h @ head^T  (K=384, 6 chunks), 384 blocks
    hgemm2<4,false,false,false,false><<<dim3(24,16),256>>>(
        h16, DM, 6, headW16, DM, nullptr, nullptr, out, FEAT, nullptr, 0);
}